// round 10
// baseline (speedup 1.0000x reference)
#include <cuda_runtime.h>
#include <cuda_bf16.h>
#include <cstdint>
#include <cfloat>

#define BB 32
#define DD 256
#define SS 2048
#define NN (BB*SS)   // 65536 rows
#define KK 4096      // codes

#define MARGIN 8e-4f
#define CAP 64

// ---------------- device globals (no allocs allowed) ----------------
__device__ float g_enorm[KK];                 // ||e_k||^2
__device__ float g_rx[NN];                    // ||x_n||^2
__device__ int   g_idx[NN];                   // argmin indices
__device__ float g_partial[8192];             // loss partials
__device__ __nv_bfloat16 g_ebf[(size_t)KK*DD];   // bf16 codebook [c][d]
__device__ int   g_ccnt[NN];                  // candidate counts
__device__ int   g_cand[(size_t)NN*CAP];      // candidate code ids (16MB)

// ---------------- helpers ----------------
__device__ __forceinline__ uint32_t smem_u32(const void* p) {
    uint32_t a;
    asm("{ .reg .u64 t; cvta.to.shared.u64 t, %1; cvt.u32.u64 %0, t; }" : "=r"(a) : "l"(p));
    return a;
}
__device__ __forceinline__ void ldm_x4(uint32_t (&r)[4], uint32_t addr) {
    asm volatile("ldmatrix.sync.aligned.m8n8.x4.shared.b16 {%0,%1,%2,%3}, [%4];"
        : "=r"(r[0]), "=r"(r[1]), "=r"(r[2]), "=r"(r[3]) : "r"(addr));
}
__device__ __forceinline__ void hmma(float (&d)[4], const uint32_t (&a)[4],
                                     uint32_t b0, uint32_t b1) {
    asm volatile("mma.sync.aligned.m16n8k16.row.col.f32.bf16.bf16.f32 "
        "{%0,%1,%2,%3}, {%4,%5,%6,%7}, {%8,%9}, {%0,%1,%2,%3};"
        : "+f"(d[0]), "+f"(d[1]), "+f"(d[2]), "+f"(d[3])
        : "r"(a[0]), "r"(a[1]), "r"(a[2]), "r"(a[3]), "r"(b0), "r"(b1));
}
#define CP16(dst, src) \
    asm volatile("cp.async.cg.shared.global [%0], [%1], 16;" :: "r"(dst), "l"(src))
#define CP_COMMIT() asm volatile("cp.async.commit_group;" ::: "memory")
#define CP_WAIT0()  asm volatile("cp.async.wait_group 0;" ::: "memory")

// monotone float<->uint encoding for atomicMin over floats
__device__ __forceinline__ unsigned fenc(float f) {
    int b = __float_as_int(f);
    return b >= 0 ? ((unsigned)b | 0x80000000u) : ~(unsigned)b;
}
__device__ __forceinline__ float fdec(unsigned u) {
    int b = (u & 0x80000000u) ? (int)(u ^ 0x80000000u) : ~(int)u;
    return __int_as_float(b);
}

// ---------------- prep kernels ----------------
__global__ void k_enorm(const float* __restrict__ cb) {
    int k = blockIdx.x * blockDim.x + threadIdx.x;
    const float* p = cb + (size_t)k * DD;
    float acc = 0.f;
    for (int d = 0; d < DD; d++) { float v = p[d]; acc = __fadd_rn(acc, __fmul_rn(v, v)); }
    g_enorm[k] = acc;
}

__global__ void k_rx(const float* __restrict__ x) {
    int n = blockIdx.x * blockDim.x + threadIdx.x;
    const float* p = x + (size_t)(n >> 11) * DD * SS + (n & 2047);
    float acc = 0.f;
    for (int d = 0; d < DD; d++) { float v = p[(size_t)d * SS]; acc = __fadd_rn(acc, __fmul_rn(v, v)); }
    g_rx[n] = acc;
    g_ccnt[n] = 0;
}

__global__ void k_ebf(const float* __restrict__ cb) {
    size_t i = (size_t)blockIdx.x * 256 + threadIdx.x;
    g_ebf[i] = __float2bfloat16(cb[i]);
}

// ---------------- K1: bf16 HMMA screen, 2-stage frag pipeline + cp.async --
#define XH_STRIDE 264
#define E_STRIDE  72                     // elements; 144B row stride (bank-clean)
#define SM_XH     0
#define SM_E0     67584
#define SM_E1     86016
#define SM_K1_TOT 104448

// load A fragments (2x ldm_x4) for absolute k-offset k0 (elements)
#define LDSM_A(Adst, k0) do { \
    ldm_x4(Adst[0], a_base + (k0) * 2); \
    ldm_x4(Adst[1], a_base + 16 * XH_STRIDE * 2 + (k0) * 2); } while (0)
// load B fragments (4x ldm_x4) for chunk-local k-step ks from buffer eb
#define LDSM_B(Bdst, eb, ks) do { \
    ldm_x4(Bdst[0], (eb) + b_off + 0 * 16 * E_STRIDE * 2 + (ks) * 32); \
    ldm_x4(Bdst[1], (eb) + b_off + 1 * 16 * E_STRIDE * 2 + (ks) * 32); \
    ldm_x4(Bdst[2], (eb) + b_off + 2 * 16 * E_STRIDE * 2 + (ks) * 32); \
    ldm_x4(Bdst[3], (eb) + b_off + 3 * 16 * E_STRIDE * 2 + (ks) * 32); } while (0)
#define HMMA_ALL(Af, Bf) do { \
    _Pragma("unroll") \
    for (int mt = 0; mt < 2; mt++) \
        _Pragma("unroll") \
        for (int nt = 0; nt < 8; nt++) \
            hmma(acc[mt][nt], Af[mt], Bf[nt >> 1][(nt & 1) * 2], \
                 Bf[nt >> 1][(nt & 1) * 2 + 1]); } while (0)

__global__ void __launch_bounds__(256, 2) k_screen(const float* __restrict__ x) {
    extern __shared__ char sm[];
    __shared__ unsigned rmin[128];     // encoded running row-min
    const uint32_t sb = smem_u32(sm);
    const int t = threadIdx.x, lane = t & 31, w = t >> 5;
    const int n0 = blockIdx.x * 128;
    const float* xbase = x + (size_t)(n0 >> 11) * DD * SS + (n0 & 2047);

    if (t < 128) rmin[t] = 0xFFFFFFFFu;

    // kick off cp.async of chunk 0 (tile 0, kc 0) into buf0
    const int lc = t >> 1, lh = t & 1;
    {
        uint32_t dst = sb + SM_E0 + lc * 144 + lh * 64;
        const char* src = (const char*)(g_ebf + (size_t)lc * 256 + lh * 32);
        CP16(dst, src); CP16(dst + 16, src + 16);
        CP16(dst + 32, src + 32); CP16(dst + 48, src + 48);
        CP_COMMIT();
    }

    // build Xh (bf16 rn) while chunk 0 streams in
    for (int i = t; i < 128 * 256; i += 256) {
        int d = i >> 7, r = i & 127;
        float v = __ldg(xbase + (size_t)d * SS + r);
        *(__nv_bfloat16*)(sm + SM_XH + (r * XH_STRIDE + d) * 2) = __float2bfloat16(v);
    }
    CP_WAIT0();
    __syncthreads();

    const int wr = w & 3, wc = w >> 2;
    const int RB = wr * 32, CB = wc * 64;

    float acc[2][8][4];
    #pragma unroll
    for (int mt = 0; mt < 2; mt++)
        #pragma unroll
        for (int nt = 0; nt < 8; nt++)
            #pragma unroll
            for (int i = 0; i < 4; i++) acc[mt][nt][i] = 0.f;

    // baked fragment addresses
    const uint32_t a_base = sb + SM_XH +
        ((RB + (lane & 7) + ((lane >> 3) & 1) * 8) * XH_STRIDE + ((lane >> 4) & 1) * 8) * 2;
    const uint32_t b_off =
        ((CB + (lane & 7) + ((lane >> 4) & 1) * 8) * E_STRIDE + ((lane >> 3) & 1) * 8) * 2;

    uint32_t A0[2][4], A1[2][4], B0[4][4], B1[4][4];
    uint32_t eb = sb + SM_E0;
    int cur = 0;

    LDSM_A(A0, 0);
    LDSM_B(B0, eb, 0);

    for (int ci = 0; ci < 128; ci++) {       // 32 tiles x 4 k-chunks(64)
        const int tt = ci >> 2, kc = ci & 3;
        // prefetch next chunk into the other buffer via cp.async
        if (ci + 1 < 128) {
            int t2 = (ci + 1) >> 2, k2 = (ci + 1) & 3;
            uint32_t dst = sb + (cur ? SM_E0 : SM_E1) + lc * 144 + lh * 64;
            const char* src = (const char*)(g_ebf +
                ((size_t)t2 * 128 + lc) * 256 + k2 * 64 + lh * 32);
            CP16(dst, src); CP16(dst + 16, src + 16);
            CP16(dst + 32, src + 32); CP16(dst + 48, src + 48);
            CP_COMMIT();
        }
        const int kb = kc * 64;
        // pipelined k-steps: LDSM(ks+1) issued before HMMA(ks)
        LDSM_A(A1, kb + 16); LDSM_B(B1, eb, 1); HMMA_ALL(A0, B0);
        LDSM_A(A0, kb + 32); LDSM_B(B0, eb, 2); HMMA_ALL(A1, B1);
        LDSM_A(A1, kb + 48); LDSM_B(B1, eb, 3); HMMA_ALL(A0, B0);
        HMMA_ALL(A1, B1);

        // tile epilogue: scores in place, capture guarded (superset invariant:
        // rmin monotone decreasing, rescue exact => result race-invariant)
        if (kc == 3) {
            const int tb = tt * 128;
            #pragma unroll
            for (int mt = 0; mt < 2; mt++) {
                float mn01 = FLT_MAX, mn23 = FLT_MAX;
                #pragma unroll
                for (int nt = 0; nt < 8; nt++) {
                    const int gcol = tb + CB + nt * 8 + (lane & 3) * 2;
                    float2 ce = __ldg((const float2*)&g_enorm[gcol]);
                    acc[mt][nt][0] = ce.x - 2.f * acc[mt][nt][0];
                    acc[mt][nt][1] = ce.y - 2.f * acc[mt][nt][1];
                    acc[mt][nt][2] = ce.x - 2.f * acc[mt][nt][2];
                    acc[mt][nt][3] = ce.y - 2.f * acc[mt][nt][3];
                    mn01 = fminf(mn01, fminf(acc[mt][nt][0], acc[mt][nt][1]));
                    mn23 = fminf(mn23, fminf(acc[mt][nt][2], acc[mt][nt][3]));
                }
                const int r0 = RB + mt * 16 + (lane >> 2);
                atomicMin(&rmin[r0], fenc(mn01));
                atomicMin(&rmin[r0 + 8], fenc(mn23));
                const float th0 = fdec(rmin[r0]) + MARGIN;
                const float th1 = fdec(rmin[r0 + 8]) + MARGIN;
                if (mn01 <= th0 || mn23 <= th1) {   // record tiles only
                    #pragma unroll
                    for (int nt = 0; nt < 8; nt++) {
                        const int gcol = tb + CB + nt * 8 + (lane & 3) * 2;
                        if (acc[mt][nt][0] <= th0) {
                            int p = atomicAdd(&g_ccnt[n0 + r0], 1);
                            if (p < CAP) g_cand[(size_t)(n0 + r0) * CAP + p] = gcol;
                        }
                        if (acc[mt][nt][1] <= th0) {
                            int p = atomicAdd(&g_ccnt[n0 + r0], 1);
                            if (p < CAP) g_cand[(size_t)(n0 + r0) * CAP + p] = gcol + 1;
                        }
                        if (acc[mt][nt][2] <= th1) {
                            int p = atomicAdd(&g_ccnt[n0 + r0 + 8], 1);
                            if (p < CAP) g_cand[(size_t)(n0 + r0 + 8) * CAP + p] = gcol;
                        }
                        if (acc[mt][nt][3] <= th1) {
                            int p = atomicAdd(&g_ccnt[n0 + r0 + 8], 1);
                            if (p < CAP) g_cand[(size_t)(n0 + r0 + 8) * CAP + p] = gcol + 1;
                        }
                    }
                }
                #pragma unroll
                for (int nt = 0; nt < 8; nt++) {
                    acc[mt][nt][0] = 0.f; acc[mt][nt][1] = 0.f;
                    acc[mt][nt][2] = 0.f; acc[mt][nt][3] = 0.f;
                }
            }
        }
        if (ci + 1 < 128) {
            CP_WAIT0();            // our prefetch group done
            __syncthreads();       // everyone done reading/writing buffers
            cur ^= 1;
            eb = sb + (cur ? SM_E1 : SM_E0);
            LDSM_A(A0, ((ci + 1) & 3) * 64);   // prime stage 0 for next chunk
            LDSM_B(B0, eb, 0);
        }
    }
}

// ---------------- K2: exact rescue over candidates (warp per row) --------
__global__ void __launch_bounds__(256) k_rescue(const float* __restrict__ x,
                                                const float* __restrict__ cb) {
    const int n = (blockIdx.x * 256 + threadIdx.x) >> 5;
    const int lane = threadIdx.x & 31;
    const float* xp = x + (size_t)(n >> 11) * DD * SS + (n & 2047);

    float xr[8];
    #pragma unroll
    for (int j = 0; j < 8; j++)
        xr[j] = __ldg(xp + (size_t)(lane + 32 * j) * SS);

    int cnt = __ldg(&g_ccnt[n]);
    if (cnt > CAP) cnt = CAP;
    const float rxv = __ldg(&g_rx[n]);

    float bd = FLT_MAX; int bi = 0x7fffffff;
    for (int i = 0; i < cnt; i++) {
        int c = __ldg(&g_cand[(size_t)n * CAP + i]);
        const float* ep = cb + (size_t)c * DD;
        float pa = 0.f;
        #pragma unroll
        for (int j = 0; j < 8; j++)
            pa = fmaf(xr[j], __ldg(ep + lane + 32 * j), pa);
        #pragma unroll
        for (int o = 16; o > 0; o >>= 1)
            pa += __shfl_down_sync(0xFFFFFFFFu, pa, o);
        pa = __shfl_sync(0xFFFFFFFFu, pa, 0);
        float ce = __ldg(&g_enorm[c]);
        float dist = __fsub_rn(__fadd_rn(rxv, ce), __fmul_rn(2.0f, pa));
        if (dist < bd || (dist == bd && c < bi)) { bd = dist; bi = c; }
    }
    if (lane == 0) g_idx[n] = bi;
}

// ---------------- output + loss (8 d per thread) --------------------------
__global__ void k_out(const float* __restrict__ x, const float* __restrict__ cb,
                      float* __restrict__ out) {
    int n = blockIdx.x * 256 + threadIdx.x;
    int d0 = blockIdx.y * 8;
    int idx = __ldg(&g_idx[n]);
    float4 q0 = __ldg((const float4*)(cb + (size_t)idx * DD + d0));
    float4 q1 = __ldg((const float4*)(cb + (size_t)idx * DD + d0 + 4));
    float q[8] = {q0.x, q0.y, q0.z, q0.w, q1.x, q1.y, q1.z, q1.w};

    size_t base = (size_t)(n >> 11) * DD * SS + (size_t)d0 * SS + (n & 2047);
    float sq = 0.f;
    #pragma unroll
    for (int dd = 0; dd < 8; dd++) {
        size_t addr = base + (size_t)dd * SS;
        float xv = __ldg(&x[addr]);
        out[addr] = q[dd];
        float df = q[dd] - xv;
        sq += df * df;
    }

    __shared__ float smr[256];
    smr[threadIdx.x] = sq;
    __syncthreads();
    #pragma unroll
    for (int s2 = 128; s2 > 0; s2 >>= 1) {
        if (threadIdx.x < s2) smr[threadIdx.x] += smr[threadIdx.x + s2];
        __syncthreads();
    }
    if (threadIdx.x == 0)
        g_partial[blockIdx.y * gridDim.x + blockIdx.x] = smr[0];
}

__global__ void k_loss(float* __restrict__ out, int out_size) {
    __shared__ double smr[256];
    int t = threadIdx.x;
    double acc = 0.0;
    for (int j = 0; j < 32; j++)
        acc += (double)g_partial[t + 256 * j];
    smr[t] = acc;
    __syncthreads();
    #pragma unroll
    for (int s2 = 128; s2 > 0; s2 >>= 1) {
        if (t < s2) smr[t] += smr[t + s2];
        __syncthreads();
    }
    if (t == 0) {
        double mse = smr[0] / (double)((size_t)NN * DD);
        out[out_size - 1] = (float)(1.25 * mse);
    }
}

// ---------------- launch ----------------
extern "C" void kernel_launch(void* const* d_in, const int* in_sizes, int n_in,
                              void* d_out, int out_size) {
    const float* x  = (const float*)d_in[0];
    const float* cb = (const float*)d_in[1];
    float* out = (float*)d_out;

    static bool attr_set = false;
    if (!attr_set) {
        cudaFuncSetAttribute(k_screen, cudaFuncAttributeMaxDynamicSharedMemorySize, SM_K1_TOT);
        attr_set = true;
    }

    k_enorm<<<KK / 256, 256>>>(cb);
    k_rx<<<NN / 256, 256>>>(x);
    k_ebf<<<(KK * DD) / 256, 256>>>(cb);
    k_screen<<<NN / 128, 256, SM_K1_TOT>>>(x);
    k_rescue<<<NN / 8, 256>>>(x, cb);
    k_out<<<dim3(NN / 256, DD / 8), 256>>>(x, cb, out);
    k_loss<<<1, 256>>>(out, out_size);
}